// round 7
// baseline (speedup 1.0000x reference)
#include <cuda_runtime.h>
#include <math.h>

// Problem constants
#define BSZ   64
#define NSEQ  2048
#define CDIM  256
#define NBASE 100
#define EPSV  1e-12f
#define WCOLS 384            // 256 q-cols + 100 raw-cols + 28 zero pad
#define RPAD  101            // odd stride -> conflict-free smem columns

// ---------------- device scratch (no allocations allowed) ----------------
__device__ float g_kn [NBASE * CDIM];     // normalized k rows
__device__ float g_r0 [NBASE];            // kn_m . bq
__device__ float g_WT [CDIM * WCOLS];     // W' transposed: [k][c'] ; c'<256 -> Wq[c'][k], 256..355 -> P[m][k]
__device__ float g_att[BSZ * NBASE];      // mask-weighted attention column sums
__device__ float g_avg[BSZ * CDIM];       // masked column sums of x

// ---------------- prep 1: kn and r0 ----------------
__global__ void prep_kn(const float* __restrict__ bw, const float* __restrict__ Wk,
                        const float* __restrict__ bk, const float* __restrict__ bq)
{
    __shared__ float bwm[CDIM];
    __shared__ float red[CDIM];
    __shared__ float inv_s;
    int m = blockIdx.x, t = threadIdx.x;

    bwm[t] = bw[m * CDIM + t];
    __syncthreads();

    float acc = bk[t];
#pragma unroll 8
    for (int j = 0; j < CDIM; ++j) acc += Wk[t * CDIM + j] * bwm[j];

    red[t] = acc * acc;
    __syncthreads();
    for (int s = 128; s > 0; s >>= 1) { if (t < s) red[t] += red[t + s]; __syncthreads(); }
    if (t == 0) inv_s = 1.f / fmaxf(sqrtf(red[0]), EPSV);
    __syncthreads();

    float knc = acc * inv_s;
    g_kn[m * CDIM + t] = knc;

    red[t] = knc * bq[t];
    __syncthreads();
    for (int s = 128; s > 0; s >>= 1) { if (t < s) red[t] += red[t + s]; __syncthreads(); }
    if (t == 0) g_r0[m] = red[0];
}

// ---------------- prep 2: build W'^T = [WqT | P^T | 0] ----------------
__global__ void prep_WT(const float* __restrict__ Wq)
{
    __shared__ float kns[CDIM];
    int cp = blockIdx.x, t = threadIdx.x;    // t indexes k
    if (cp < CDIM) {
        g_WT[t * WCOLS + cp] = Wq[cp * CDIM + t];
    } else if (cp < CDIM + NBASE) {
        int m = cp - CDIM;
        kns[t] = g_kn[m * CDIM + t];
        __syncthreads();
        float acc = 0.f;
#pragma unroll 8
        for (int c = 0; c < CDIM; ++c) acc += kns[c] * Wq[c * CDIM + t];  // coalesced over t
        g_WT[t * WCOLS + cp] = acc;
    } else {
        g_WT[t * WCOLS + cp] = 0.f;
    }
}

// ---------------- main fused kernel: 1 CTA per 128-row tile ----------------
__global__ __launch_bounds__(256, 1)
void main_kernel(const float* __restrict__ x, const float* __restrict__ mask,
                 const float* __restrict__ bq)
{
    extern __shared__ float sm[];
    float* xs   = sm;                      // 128*256            = 32768 floats
    float* ws   = xs   + 128 * CDIM;       // 256*32             =  8192
    float* raws = ws   + 8192;             // 128*101            = 12928
    float* bsm  = raws + 128 * RPAD;       // 384
    float* mk   = bsm  + WCOLS;            // 128
    float* ssq  = mk   + 128;              // 128

    const int tid  = threadIdx.x;
    const int b    = blockIdx.x >> 4;
    const int tile = blockIdx.x & 15;

    // load x tile (layout identical to global: straight float4 copy)
    const float4* xg  = (const float4*)(x + ((size_t)b * NSEQ + (size_t)tile * 128) * CDIM);
    float4*       xs4 = (float4*)xs;
#pragma unroll
    for (int v = 0; v < 32; ++v) xs4[tid + v * 256] = xg[tid + v * 256];

    if (tid < 128) {
        mk[tid]  = mask[b * NSEQ + tile * 128 + tid];
        ssq[tid] = 0.f;
    }
    for (int i = tid; i < WCOLS; i += 256)
        bsm[i] = (i < CDIM) ? bq[i] : ((i < CDIM + NBASE) ? g_r0[i - CDIM] : 0.f);

    const int tx = tid & 7;        // 8 col-groups of 4
    const int ty = tid >> 3;       // 32 row-groups of 4

    for (int ch = 0; ch < 12; ++ch) {
        const int c0 = ch * 32;
        __syncthreads();           // covers initial loads + previous chunk's ws use
        for (int v = tid; v < 8192; v += 256) {
            int k = v >> 5, c = v & 31;
            ws[v] = g_WT[k * WCOLS + c0 + c];
        }
        __syncthreads();

        float acc[4][4] = {};
#pragma unroll 2
        for (int k = 0; k < CDIM; k += 4) {
            float wv[4][4];
#pragma unroll
            for (int kk = 0; kk < 4; ++kk) {
                float4 t4 = *(const float4*)(ws + (k + kk) * 32 + tx * 4);
                wv[kk][0] = t4.x; wv[kk][1] = t4.y; wv[kk][2] = t4.z; wv[kk][3] = t4.w;
            }
#pragma unroll
            for (int i = 0; i < 4; ++i) {
                float4 t4 = *(const float4*)(xs + (ty * 4 + i) * CDIM + k);
                float xr[4] = {t4.x, t4.y, t4.z, t4.w};
#pragma unroll
                for (int kk = 0; kk < 4; ++kk)
#pragma unroll
                    for (int j = 0; j < 4; ++j)
                        acc[i][j] = fmaf(xr[kk], wv[kk][j], acc[i][j]);
            }
        }

        if (ch < 8) {
            // q columns: accumulate per-row sum of squares (q = acc + bq)
#pragma unroll
            for (int i = 0; i < 4; ++i) {
                float s = 0.f;
#pragma unroll
                for (int j = 0; j < 4; ++j) {
                    float qv = acc[i][j] + bsm[c0 + tx * 4 + j];
                    s += qv * qv;
                }
                s += __shfl_xor_sync(0xffffffffu, s, 1);
                s += __shfl_xor_sync(0xffffffffu, s, 2);
                s += __shfl_xor_sync(0xffffffffu, s, 4);
                if (tx == 0) ssq[ty * 4 + i] += s;   // unique owner per row
            }
        } else {
            // raw columns: store raw_m = acc + r0_m
            const int m0 = c0 - CDIM;
#pragma unroll
            for (int i = 0; i < 4; ++i)
#pragma unroll
                for (int j = 0; j < 4; ++j) {
                    int m = m0 + tx * 4 + j;
                    if (m < NBASE)
                        raws[(ty * 4 + i) * RPAD + m] = acc[i][j] + bsm[c0 + tx * 4 + j];
                }
        }
    }
    __syncthreads();

    // branch 1: masked column sums of x (xs still intact)
    {
        float s = 0.f;
#pragma unroll 8
        for (int r = 0; r < 128; ++r) s += mk[r] * xs[r * CDIM + tid];
        atomicAdd(&g_avg[b * CDIM + tid], s);
    }

    // per-row softmax over NB logits, scaled by mask[row]
    if (tid < 128) {
        const int r = tid;
        float invq = 1.f / fmaxf(sqrtf(ssq[r]), EPSV);
        float mx = -1e30f;
        for (int m = 0; m < NBASE; ++m) mx = fmaxf(mx, raws[r * RPAD + m] * invq);
        float sum = 0.f;
        for (int m = 0; m < NBASE; ++m) {
            float e = expf(raws[r * RPAD + m] * invq - mx);
            raws[r * RPAD + m] = e;
            sum += e;
        }
        float scl = mk[r] / sum;
        for (int m = 0; m < NBASE; ++m) raws[r * RPAD + m] *= scl;
    }
    __syncthreads();

    // column-reduce mask-weighted attention into g_att
    if (tid < NBASE) {
        float s = 0.f;
#pragma unroll 8
        for (int r = 0; r < 128; ++r) s += raws[r * RPAD + tid];
        atomicAdd(&g_att[b * NBASE + tid], s);
    }
}

// ---------------- final combine: 1 CTA per batch ----------------
__global__ void final_kernel(const float* __restrict__ bw, const float* __restrict__ mask,
                             const float* __restrict__ w_avg, const float* __restrict__ w_att,
                             float* __restrict__ out)
{
    __shared__ float red[256];
    __shared__ float atts[NBASE];
    __shared__ float inv_s;
    int b = blockIdx.x, t = threadIdx.x;

    float ms = 0.f;
    for (int n = t; n < NSEQ; n += 256) ms += mask[b * NSEQ + n];
    red[t] = ms;
    __syncthreads();
    for (int s = 128; s > 0; s >>= 1) { if (t < s) red[t] += red[t + s]; __syncthreads(); }
    if (t == 0) inv_s = 1.f / fmaxf(red[0], EPSV);
    if (t < NBASE) atts[t] = g_att[b * NBASE + t];
    __syncthreads();

    float invd = inv_s;
    float wn2 = 0.f;
#pragma unroll 4
    for (int m = 0; m < NBASE; ++m) wn2 += atts[m] * bw[m * CDIM + t];

    float wn1 = g_avg[b * CDIM + t] * invd * w_avg[t];
    out[b * CDIM + t] = 0.5f * (wn1 + wn2 * invd * w_att[t]);
}

// ---------------- launch ----------------
extern "C" void kernel_launch(void* const* d_in, const int* in_sizes, int n_in,
                              void* d_out, int out_size)
{
    const float* bw    = (const float*)d_in[0];
    const float* x     = (const float*)d_in[1];
    const float* mask  = (const float*)d_in[2];
    const float* Wq    = (const float*)d_in[3];
    const float* bq    = (const float*)d_in[4];
    const float* Wk    = (const float*)d_in[5];
    const float* bk    = (const float*)d_in[6];
    const float* w_avg = (const float*)d_in[7];
    const float* w_att = (const float*)d_in[8];
    float* out = (float*)d_out;

    void *p_att = 0, *p_avg = 0;
    cudaGetSymbolAddress(&p_att, g_att);
    cudaGetSymbolAddress(&p_avg, g_avg);
    cudaMemsetAsync(p_att, 0, sizeof(float) * BSZ * NBASE, 0);
    cudaMemsetAsync(p_avg, 0, sizeof(float) * BSZ * CDIM, 0);

    prep_kn<<<NBASE, 256>>>(bw, Wk, bk, bq);
    prep_WT<<<WCOLS, 256>>>(Wq);

    int smem = (128 * CDIM + 8192 + 128 * RPAD + WCOLS + 128 + 128) * (int)sizeof(float); // 218112 B
    cudaFuncSetAttribute(main_kernel, cudaFuncAttributeMaxDynamicSharedMemorySize, smem);
    main_kernel<<<BSZ * 16, 256, smem>>>(x, mask, bq);

    final_kernel<<<BSZ, 256>>>(bw, mask, w_avg, w_att, out);
}

// round 13
// speedup vs baseline: 4.3925x; 4.3925x over previous
#include <cuda_runtime.h>
#include <cuda_bf16.h>
#include <math.h>
#include <stdint.h>

#define BSZ   64
#define NSEQ  2048
#define CDIM  256
#define NBASE 100
#define EPSV  1e-12f
#define TILES 1024
#define NCH   45          // 360 output cols / 8
#define RSTR  105         // raws row stride (floats)

// ---------------- device scratch ----------------
__device__ uint4    g_xa[TILES * 4096];        // A fragments: [tile][warp8][kstep16][lane32] = {a0,a1,a2,a3}
__device__ uint32_t g_Bp[NCH * 16 * 32 * 2];   // B fragments: [chunk][kstep][lane]{b0,b1}  (184320 B)
__device__ float g_kn [NBASE * CDIM];
__device__ float g_r0 [104];                   // zero-init covers m>=100
__device__ float g_att[BSZ * NBASE];
__device__ float g_avg[BSZ * CDIM];
__device__ float g_msum[BSZ];

#define MMA16816(c0,c1,c2,c3,a0,a1,a2,a3,b0,b1)                                   \
    asm volatile("mma.sync.aligned.m16n8k16.row.col.f32.bf16.bf16.f32 "           \
                 "{%0,%1,%2,%3}, {%4,%5,%6,%7}, {%8,%9}, {%0,%1,%2,%3};"          \
                 : "+f"(c0), "+f"(c1), "+f"(c2), "+f"(c3)                         \
                 : "r"(a0), "r"(a1), "r"(a2), "r"(a3), "r"(b0), "r"(b1))

// ---------------- prep 1: kn, r0 ----------------
__global__ void prep_kn(const float* __restrict__ bw, const float* __restrict__ Wk,
                        const float* __restrict__ bk, const float* __restrict__ bq)
{
    __shared__ float bwm[CDIM];
    __shared__ float red[CDIM];
    __shared__ float inv_s;
    int m = blockIdx.x, t = threadIdx.x;
    bwm[t] = bw[m * CDIM + t];
    __syncthreads();
    float acc = bk[t];
#pragma unroll 8
    for (int j = 0; j < CDIM; ++j) acc += Wk[t * CDIM + j] * bwm[j];
    red[t] = acc * acc;
    __syncthreads();
    for (int s = 128; s > 0; s >>= 1) { if (t < s) red[t] += red[t + s]; __syncthreads(); }
    if (t == 0) inv_s = 1.f / fmaxf(sqrtf(red[0]), EPSV);
    __syncthreads();
    float knc = acc * inv_s;
    g_kn[m * CDIM + t] = knc;
    red[t] = knc * bq[t];
    __syncthreads();
    for (int s = 128; s > 0; s >>= 1) { if (t < s) red[t] += red[t + s]; __syncthreads(); }
    if (t == 0) g_r0[m] = red[0];
}

// ---------------- prep 2: build fragment-packed B = [Wq rows | P rows | 0] ----------------
// Output col cp: cp<256 -> Wq[cp][k]; 256<=cp<356 -> P[cp-256][k]=sum_c kn[m][c]Wq[c][k]; else 0
__global__ void prep_B(const float* __restrict__ Wq)
{
    __shared__ float kns[CDIM];
    __shared__ float ps[CDIM];
    int cp = blockIdx.x, tid = threadIdx.x;
    float w0 = 0.f, w1 = 0.f;
    if (cp < CDIM) {
        if (tid < 128) { w0 = Wq[cp * CDIM + 2 * tid]; w1 = Wq[cp * CDIM + 2 * tid + 1]; }
    } else {
        int m = cp - CDIM;
        if (m < NBASE) {
            kns[tid] = g_kn[m * CDIM + tid];
            __syncthreads();
            float acc = 0.f;
#pragma unroll 8
            for (int c = 0; c < CDIM; ++c) acc += kns[c] * Wq[c * CDIM + tid];
            ps[tid] = acc;
            __syncthreads();
            if (tid < 128) { w0 = ps[2 * tid]; w1 = ps[2 * tid + 1]; }
        }
    }
    if (tid < 128) {
        __nv_bfloat162 bf = __floats2bfloat162_rn(w0, w1);
        int c = cp >> 3;
        int l = (cp & 7) * 4 + (tid & 3);
        int w = (tid >> 2) & 1;
        int s = tid >> 3;
        g_Bp[((c * 16 + s) * 32 + l) * 2 + w] = *(uint32_t*)&bf;
    }
}

// ---------------- conversion: x -> A fragments + branch1 sums + mask sums ----------------
__global__ __launch_bounds__(256) void conv_kernel(const float* __restrict__ x,
                                                   const float* __restrict__ mask)
{
    extern __shared__ float cs[];
    uint32_t* st  = (uint32_t*)cs;          // [128][129] bf16x2 pairs
    float* mks    = cs + 128 * 129;         // 128
    float* csum   = mks + 128;              // 256

    const int tid = threadIdx.x, blk = blockIdx.x;
    const int b = blk >> 4;
    const size_t row0 = (size_t)blk * 128;

    if (tid < 128) mks[tid] = mask[row0 + tid];
    csum[tid] = 0.f;
    __syncthreads();

    const int p = tid & 127, h = tid >> 7;
    float s0 = 0.f, s1 = 0.f;
    const float* xr = x + row0 * CDIM;
#pragma unroll 4
    for (int it = 0; it < 64; ++it) {
        int r = h + it * 2;
        float f0 = xr[(size_t)r * CDIM + 2 * p];
        float f1 = xr[(size_t)r * CDIM + 2 * p + 1];
        float mv = mks[r];
        s0 += mv * f0; s1 += mv * f1;
        __nv_bfloat162 bf = __floats2bfloat162_rn(f0, f1);
        st[r * 129 + p] = *(uint32_t*)&bf;
    }
    atomicAdd(&csum[2 * p], s0);
    atomicAdd(&csum[2 * p + 1], s1);
    __syncthreads();

    // emit A fragments: [warp w][kstep ks][lane] = {x[r0][kp], x[r0+8][kp], x[r0][kp+4], x[r0+8][kp+4]}
    uint4* out = g_xa + (size_t)blk * 4096;
    for (int i = tid; i < 4096; i += 256) {
        int lane = i & 31, ks = (i >> 5) & 15, w = i >> 9;
        int r0 = w * 16 + (lane >> 2);
        int kp = (lane & 3) + ks * 8;
        uint4 v;
        v.x = st[r0 * 129 + kp];
        v.y = st[(r0 + 8) * 129 + kp];
        v.z = st[r0 * 129 + kp + 4];
        v.w = st[(r0 + 8) * 129 + kp + 4];
        out[i] = v;
    }
    atomicAdd(&g_avg[b * CDIM + tid], csum[tid]);
    __syncthreads();
    for (int s = 64; s > 0; s >>= 1) { if (tid < s) mks[tid] += mks[tid + s]; __syncthreads(); }
    if (tid == 0) atomicAdd(&g_msum[b], mks[0]);
}

// ---------------- main: mma.sync GEMM + softmax + reductions ----------------
__global__ __launch_bounds__(256, 1)
void main_kernel(const float* __restrict__ mask, const float* __restrict__ bq)
{
    extern __shared__ uint8_t sm[];
    uint32_t* Bs = (uint32_t*)sm;                  // 46080 words = 184320 B
    float* raws  = (float*)sm;                     // reused after MMA: [128][RSTR]
    float* bqs   = (float*)(sm + 184320);          // 256
    float* r0s   = bqs + 256;                      // 104
    float* mks   = r0s + 104;                      // 128
    float* ssqs  = mks + 128;                      // 128

    const int tid  = threadIdx.x;
    const int wid  = tid >> 5;
    const int lane = tid & 31;
    const int blk  = blockIdx.x;
    const int b    = blk >> 4;

    // copy packed B into SMEM
    {
        const uint4* src = (const uint4*)g_Bp;
        uint4* dst = (uint4*)sm;
        for (int i = tid; i < 11520; i += 256) dst[i] = src[i];
    }
    bqs[tid] = bq[tid];
    if (tid < 104) r0s[tid] = g_r0[tid];
    if (tid < 128) mks[tid] = mask[blk * 128 + tid];

    // A fragments -> registers (coalesced LDG.128)
    uint4 a[16];
    {
        const uint4* ap = g_xa + (size_t)blk * 4096 + wid * 512 + lane;
#pragma unroll
        for (int s = 0; s < 16; ++s) a[s] = ap[s * 32];
    }
    __syncthreads();

    const int lq = (lane & 3) * 2;

    // q chunks (n = 0..255): fold into sum-of-squares
    float ssq0 = 0.f, ssq1 = 0.f;
    for (int ch = 0; ch < 32; ++ch) {
        float c0 = 0.f, c1 = 0.f, c2 = 0.f, c3 = 0.f;
        const uint32_t* bp = Bs + ch * 1024 + lane * 2;
#pragma unroll
        for (int s = 0; s < 16; ++s) {
            uint2 bb = *(const uint2*)(bp + s * 64);
            MMA16816(c0, c1, c2, c3, a[s].x, a[s].y, a[s].z, a[s].w, bb.x, bb.y);
        }
        float bl0 = bqs[ch * 8 + lq];
        float bl1 = bqs[ch * 8 + lq + 1];
        c0 += bl0; c1 += bl1; c2 += bl0; c3 += bl1;
        ssq0 += c0 * c0 + c1 * c1;
        ssq1 += c2 * c2 + c3 * c3;
    }

    // raw chunks (n = 256..359) -> keep in registers
    float rawv[13][4];
#pragma unroll
    for (int j = 0; j < 13; ++j) {
        float c0 = 0.f, c1 = 0.f, c2 = 0.f, c3 = 0.f;
        const uint32_t* bp = Bs + (32 + j) * 1024 + lane * 2;
#pragma unroll
        for (int s = 0; s < 16; ++s) {
            uint2 bb = *(const uint2*)(bp + s * 64);
            MMA16816(c0, c1, c2, c3, a[s].x, a[s].y, a[s].z, a[s].w, bb.x, bb.y);
        }
        rawv[j][0] = c0; rawv[j][1] = c1; rawv[j][2] = c2; rawv[j][3] = c3;
    }
    __syncthreads();   // B dead; smem becomes raws

    // ssq: reduce over the 4 lanes sharing a row; unique owner writes
    ssq0 += __shfl_xor_sync(0xffffffffu, ssq0, 1);
    ssq0 += __shfl_xor_sync(0xffffffffu, ssq0, 2);
    ssq1 += __shfl_xor_sync(0xffffffffu, ssq1, 1);
    ssq1 += __shfl_xor_sync(0xffffffffu, ssq1, 2);
    const int r0 = wid * 16 + (lane >> 2);
    if ((lane & 3) == 0) { ssqs[r0] = ssq0; ssqs[r0 + 8] = ssq1; }

    // raw values -> raws smem (m = 0..103)
#pragma unroll
    for (int j = 0; j < 13; ++j) {
        int m0 = j * 8 + lq;
        raws[r0 * RSTR + m0]           = rawv[j][0];
        raws[r0 * RSTR + m0 + 1]       = rawv[j][1];
        raws[(r0 + 8) * RSTR + m0]     = rawv[j][2];
        raws[(r0 + 8) * RSTR + m0 + 1] = rawv[j][3];
    }
    __syncthreads();

    // per-row softmax over 100 logits, scaled by mask
    if (tid < 128) {
        const int r = tid;
        float inv = 1.f / fmaxf(sqrtf(ssqs[r]), EPSV);
        float lg[100];
        float mx = -1e30f;
#pragma unroll
        for (int m = 0; m < 100; ++m) {
            lg[m] = (raws[r * RSTR + m] + r0s[m]) * inv;
            mx = fmaxf(mx, lg[m]);
        }
        float sum = 0.f;
#pragma unroll
        for (int m = 0; m < 100; ++m) {
            lg[m] = __expf(lg[m] - mx);
            sum += lg[m];
        }
        float scl = mks[r] / sum;
#pragma unroll
        for (int m = 0; m < 100; ++m) raws[r * RSTR + m] = lg[m] * scl;
    }
    __syncthreads();

    // column-reduce mask-weighted attention
    if (tid < NBASE) {
        float s = 0.f;
#pragma unroll 8
        for (int r = 0; r < 128; ++r) s += raws[r * RSTR + tid];
        atomicAdd(&g_att[b * NBASE + tid], s);
    }
}

// ---------------- final combine ----------------
__global__ void final_kernel(const float* __restrict__ bw,
                             const float* __restrict__ w_avg, const float* __restrict__ w_att,
                             float* __restrict__ out)
{
    __shared__ float atts[NBASE];
    int b = blockIdx.x, t = threadIdx.x;
    if (t < NBASE) atts[t] = g_att[b * NBASE + t];
    __syncthreads();
    float invd = 1.f / fmaxf(g_msum[b], EPSV);
    float wn2 = 0.f;
#pragma unroll 4
    for (int m = 0; m < NBASE; ++m) wn2 += atts[m] * bw[m * CDIM + t];
    float wn1 = g_avg[b * CDIM + t] * invd * w_avg[t];
    out[b * CDIM + t] = 0.5f * (wn1 + wn2 * invd * w_att[t]);
}

// ---------------- launch ----------------
extern "C" void kernel_launch(void* const* d_in, const int* in_sizes, int n_in,
                              void* d_out, int out_size)
{
    const float* bw    = (const float*)d_in[0];
    const float* x     = (const float*)d_in[1];
    const float* mask  = (const float*)d_in[2];
    const float* Wq    = (const float*)d_in[3];
    const float* bq    = (const float*)d_in[4];
    const float* Wk    = (const float*)d_in[5];
    const float* bk    = (const float*)d_in[6];
    const float* w_avg = (const float*)d_in[7];
    const float* w_att = (const float*)d_in[8];
    float* out = (float*)d_out;

    void *p_att = 0, *p_avg = 0, *p_ms = 0;
    cudaGetSymbolAddress(&p_att, g_att);
    cudaGetSymbolAddress(&p_avg, g_avg);
    cudaGetSymbolAddress(&p_ms,  g_msum);
    cudaMemsetAsync(p_att, 0, sizeof(float) * BSZ * NBASE, 0);
    cudaMemsetAsync(p_avg, 0, sizeof(float) * BSZ * CDIM, 0);
    cudaMemsetAsync(p_ms,  0, sizeof(float) * BSZ, 0);

    prep_kn<<<NBASE, 256>>>(bw, Wk, bk, bq);
    prep_B<<<360, 256>>>(Wq);

    int conv_smem = (128 * 129 + 128 + 256) * (int)sizeof(float);   // 67584
    cudaFuncSetAttribute(conv_kernel, cudaFuncAttributeMaxDynamicSharedMemorySize, conv_smem);
    conv_kernel<<<TILES, 256, conv_smem>>>(x, mask);

    int main_smem = 184320 + (256 + 104 + 128 + 128) * (int)sizeof(float);  // 186784
    cudaFuncSetAttribute(main_kernel, cudaFuncAttributeMaxDynamicSharedMemorySize, main_smem);
    main_kernel<<<TILES, 256, main_smem>>>(mask, bq);

    final_kernel<<<BSZ, 256>>>(bw, w_avg, w_att, out);
}